// round 12
// baseline (speedup 1.0000x reference)
#include <cuda_runtime.h>

// Problem constants
#define BB 65536
#define DD 256
#define KK 32
#define TM 64
#define NBLK (BB / TM)   // 1024
#define BD (BB * DD)

// Device scratch (no cudaMalloc allowed)
__device__ float g_G1[KK * KK];                    // W . U^T
__device__ float g_G2[KK * KK];                    // W . W^T
__device__ __align__(16) float g_uhat[KK * DD];    // [k][d]
__device__ __align__(16) float g_WT[DD * KK];      // W transposed [d][k]

// W^T in constant memory: uniform-address reads use the constant port
// (LDCU/LDC), bypassing the L1 crossbar entirely in phase 1.
__constant__ __align__(16) float c_WT[DD * KK];

typedef unsigned long long ull;

// ---------- f32x2 helpers ----------
__device__ __forceinline__ ull ffma2(ull a, ull b, ull c) {
    ull d;
    asm("fma.rn.f32x2 %0, %1, %2, %3;" : "=l"(d) : "l"(a), "l"(b), "l"(c));
    return d;
}
__device__ __forceinline__ ull packf2(float x, float y) {
    ull r;
    asm("mov.b64 %0, {%1, %2};" : "=l"(r) : "f"(x), "f"(y));
    return r;
}

// fast accurate tanh: 1 - 2/(exp(2x)+1)
__device__ __forceinline__ float ftanh(float x) {
    float e = __expf(2.0f * x);
    return 1.0f - __fdividef(2.0f, e + 1.0f);
}

__device__ __forceinline__ float softplus(float x) {
    return fmaxf(x, 0.f) + log1pf(expf(-fabsf(x)));
}

// ---------- Gram kernel: G1[k][:], G2[k][:], uhat_k, W^T  (block = k) ----------
__global__ __launch_bounds__(256, 4)
void k_gram(const float* __restrict__ u, const float* __restrict__ w) {
    __shared__ float ws[DD];
    __shared__ float sdiag[2];
    const int k = blockIdx.x, t = threadIdx.x;
    ws[t] = w[k * DD + t];
    __syncthreads();

    g_WT[t * KK + k] = ws[t];

    const int j = t >> 3, s = t & 7;
    {
        const float* up  = u + j * DD + s * 32;
        const float* wp2 = w + j * DD + s * 32;
        const float* wsp = ws + s * 32;
        float p1 = 0.f, p2 = 0.f;
        #pragma unroll
        for (int i = 0; i < 32; ++i) {
            float wv = wsp[i];
            p1 = fmaf(wv, up[i], p1);
            p2 = fmaf(wv, wp2[i], p2);
        }
        #pragma unroll
        for (int o = 1; o <= 4; o <<= 1) {
            p1 += __shfl_xor_sync(0xffffffffu, p1, o);
            p2 += __shfl_xor_sync(0xffffffffu, p2, o);
        }
        if (s == 0) {
            g_G1[k * KK + j] = p1;
            g_G2[k * KK + j] = p2;
            if (j == k) { sdiag[0] = p1; sdiag[1] = p2; }
        }
    }
    __syncthreads();

    float wu = sdiag[0], ww = sdiag[1];
    float alpha = (softplus(wu) - 1.0f - wu) / ww;
    g_uhat[k * DD + t] = fmaf(alpha, ws[t], u[k * DD + t]);
}

// ---------- Main monolith: 256 threads, TM=64, 2 blocks/SM ----------
// smem (floats):
//  XS : 0      X tile [r][d] stride 260 (float4-clean)   = 16640
//              (phase 3: first 8192 floats alias UH = uhat [k][d])
//  TS : 16640  t [r][k] stride 36                        = 2304
//  CS : 18944  C [r][k] stride 34                        = 2176
//  AS : 21120  A[k][j]                                   = 1024
//  AL : 22144  alpha[32],  BS : 22176 b[32]
// total 22208 floats = 88832 B -> 2 blocks/SM, ~50 KB L1D left
#define OFF_XS 0
#define OFF_UH 0          // aliases XS (X is dead before uhat is staged)
#define OFF_TS 16640
#define OFF_CS 18944
#define OFF_AS 21120
#define OFF_AL 22144
#define OFF_BS 22176
#define SMEM_FLOATS 22208

__global__ __launch_bounds__(256, 2)
void nf_main(const float* __restrict__ X, const float* __restrict__ bvec,
             float* __restrict__ out) {
    extern __shared__ float sm[];
    float* XS = sm + OFF_XS;
    float* UH = sm + OFF_UH;
    float* TS = sm + OFF_TS;
    float* CS = sm + OFF_CS;
    float* AS = sm + OFF_AS;
    float* AL = sm + OFF_AL;
    float* BS = sm + OFF_BS;

    const int t = threadIdx.x;
    const int r0 = blockIdx.x * TM;

    // ---- Prologue: stage X (float4, conflict-free), alpha, b ----
    {
        const float4* Xb4 = (const float4*)(X + (size_t)r0 * DD);
        #pragma unroll
        for (int i = t; i < TM * DD / 4; i += 256) {
            int r = i >> 6, d4 = i & 63;
            *(float4*)&XS[r * 260 + d4 * 4] = Xb4[i];
        }
        if (t < KK) {
            float wu = g_G1[t * (KK + 1)];
            float ww = g_G2[t * (KK + 1)];
            AL[t] = (softplus(wu) - 1.0f - wu) / ww;
            BS[t] = bvec[t];
        }
    }
    __syncthreads();

    // A = G1 + alpha_j * G2 (consumed after a later barrier)
    #pragma unroll
    for (int e = t; e < KK * KK; e += 256)
        AS[e] = g_G1[e] + AL[e & 31] * g_G2[e];

    // ---- Phase 1: C = X . W^T, W from constant memory ----
    // warp = (row-half rh, k-group kg of 8); lane = row within half.
    // Per 4-d group: 1 LDS.128 (x) + constant-port W -> 16 FFMA2.
    {
        const int wp = t >> 5, lane = t & 31;
        const int rh = wp >> 2, kg = wp & 3;
        const int row = rh * 32 + lane;
        ull c0 = 0ull, c1 = 0ull, c2 = 0ull, c3 = 0ull;
        const float* xrow = XS + row * 260;
        // row d of c_WT = 32 floats = 8 ulonglong2; warp's 8 k start at kg*2
        const ulonglong2* cw = ((const ulonglong2*)c_WT) + kg * 2;
        #pragma unroll 16
        for (int d = 0; d < DD; d += 4) {
            float4 xv = *(const float4*)(xrow + d);
            #pragma unroll
            for (int j = 0; j < 4; ++j) {
                ulonglong2 wa = cw[(d + j) * 8];
                ulonglong2 wb = cw[(d + j) * 8 + 1];
                float xj = (&xv.x)[j];
                ull xx = packf2(xj, xj);
                c0 = ffma2(xx, wa.x, c0);
                c1 = ffma2(xx, wa.y, c1);
                c2 = ffma2(xx, wb.x, c2);
                c3 = ffma2(xx, wb.y, c3);
            }
        }
        float* cr = CS + row * 34 + kg * 8;
        *(ull*)&cr[0] = c0;
        *(ull*)&cr[2] = c1;
        *(ull*)&cr[4] = c2;
        *(ull*)&cr[6] = c3;
    }
    __syncthreads();

    // ---- Phase 2: warps 0-1 recurrence; warps 2-7 stage uhat over XS ----
    if (t < TM) {
        const int row = t;
        float tl[KK];
        #pragma unroll
        for (int k = 0; k < KK; ++k) {
            float lin = CS[row * 34 + k] + BS[k];
            #pragma unroll
            for (int j = 0; j < k; ++j)
                lin = fmaf(AS[k * KK + j], tl[j], lin);
            float tk = ftanh(lin);
            tl[k] = tk;
            TS[row * 36 + k] = tk;
            float akk = AS[k * (KK + 1)];
            out[BD + k * BB + r0 + row] =
                __logf(fabsf(fmaf(1.0f - tk * tk, akk, 1.0f)) + 1e-8f);
        }
    } else {
        const float4* U4 = (const float4*)g_uhat;
        float4* UH4 = (float4*)UH;
        for (int i = t - TM; i < KK * DD / 4; i += 256 - TM)
            UH4[i] = U4[i];
    }
    __syncthreads();

    // ---- Phase 3: Z = X + T . Uhat ----
    // warp owns 8 rows; lane owns columns c0..c0+3 and c1..c1+3.
    // Accumulators init from global X (coalesced; XS is now UH).
    {
        const int lane = t & 31, wp = t >> 5;
        const int c0 = lane * 4, c1 = 128 + lane * 4;
        const int rb = wp * 8;
        ulonglong2 a[8][2];
        #pragma unroll
        for (int r = 0; r < 8; ++r) {
            const float* xr = X + (size_t)(r0 + rb + r) * DD;
            a[r][0] = *(const ulonglong2*)(xr + c0);
            a[r][1] = *(const ulonglong2*)(xr + c1);
        }
        #pragma unroll 4
        for (int kh = 0; kh < 16; ++kh) {       // 2 k per step
            const int k0 = kh * 2;
            float2 tv[8];
            #pragma unroll
            for (int r = 0; r < 8; ++r)
                tv[r] = *(const float2*)&TS[(rb + r) * 36 + k0];
            #pragma unroll
            for (int kk = 0; kk < 2; ++kk) {
                const int k = k0 + kk;
                ulonglong2 u0 = *(const ulonglong2*)&UH[k * DD + c0];
                ulonglong2 u1 = *(const ulonglong2*)&UH[k * DD + c1];
                #pragma unroll
                for (int r = 0; r < 8; ++r) {
                    float ts = kk ? tv[r].y : tv[r].x;
                    ull tt = packf2(ts, ts);
                    a[r][0].x = ffma2(tt, u0.x, a[r][0].x);
                    a[r][0].y = ffma2(tt, u0.y, a[r][0].y);
                    a[r][1].x = ffma2(tt, u1.x, a[r][1].x);
                    a[r][1].y = ffma2(tt, u1.y, a[r][1].y);
                }
            }
        }
        #pragma unroll
        for (int r = 0; r < 8; ++r) {
            float* zr = out + (size_t)(r0 + rb + r) * DD;
            *(ulonglong2*)(zr + c0) = a[r][0];
            *(ulonglong2*)(zr + c1) = a[r][1];
        }
    }
}

extern "C" void kernel_launch(void* const* d_in, const int* in_sizes, int n_in,
                              void* d_out, int out_size) {
    const float* X = (const float*)d_in[0];
    // d_in[1] = h (unused)
    const float* u = (const float*)d_in[2];
    const float* w = (const float*)d_in[3];
    const float* b = (const float*)d_in[4];
    float* out = (float*)d_out;

    cudaFuncSetAttribute(nf_main, cudaFuncAttributeMaxDynamicSharedMemorySize,
                         SMEM_FLOATS * (int)sizeof(float));

    k_gram<<<KK, 256>>>(u, w);

    // W^T -> constant memory (D2D async memcpy: graph-capturable, no alloc)
    void* wt_dev = nullptr;
    cudaGetSymbolAddress(&wt_dev, g_WT);
    cudaMemcpyToSymbolAsync(c_WT, wt_dev, DD * KK * sizeof(float), 0,
                            cudaMemcpyDeviceToDevice, 0);

    nf_main<<<NBLK, 256, SMEM_FLOATS * sizeof(float)>>>(X, b, out);
}

// round 13
// speedup vs baseline: 1.4212x; 1.4212x over previous
#include <cuda_runtime.h>

// Problem constants
#define BB 65536
#define DD 256
#define KK 32
#define TM 64
#define NBLK (BB / TM)   // 1024
#define BD (BB * DD)

// Device scratch (no cudaMalloc allowed)
__device__ float g_G1[KK * KK];                    // W . U^T
__device__ float g_G2[KK * KK];                    // W . W^T
__device__ __align__(16) float g_A[KK * KK];       // A[k][j] = w_k . uhat_j
__device__ __align__(16) float g_uhat[KK * DD];    // [k][d]
__device__ __align__(16) float g_WT[DD * KK];      // W transposed [d][k]

typedef unsigned long long ull;

// ---------- f32x2 helpers ----------
__device__ __forceinline__ ull ffma2(ull a, ull b, ull c) {
    ull d;
    asm("fma.rn.f32x2 %0, %1, %2, %3;" : "=l"(d) : "l"(a), "l"(b), "l"(c));
    return d;
}
__device__ __forceinline__ ull packf2(float x, float y) {
    ull r;
    asm("mov.b64 %0, {%1, %2};" : "=l"(r) : "f"(x), "f"(y));
    return r;
}

// fast accurate tanh: 1 - 2/(exp(2x)+1)
__device__ __forceinline__ float ftanh(float x) {
    float e = __expf(2.0f * x);
    return 1.0f - __fdividef(2.0f, e + 1.0f);
}

__device__ __forceinline__ float softplus(float x) {
    return fmaxf(x, 0.f) + log1pf(expf(-fabsf(x)));
}

// ---------- Gram kernel: G1[k][:], G2[k][:], uhat_k, W^T  (block = k) ----------
__global__ __launch_bounds__(256, 4)
void k_gram(const float* __restrict__ u, const float* __restrict__ w) {
    __shared__ float ws[DD];
    const int k = blockIdx.x, t = threadIdx.x;
    float wv_t = w[k * DD + t];
    ws[t] = wv_t;
    g_WT[t * KK + k] = wv_t;
    __syncthreads();

    const int j = t >> 3, s = t & 7;
    {
        const float* up  = u + j * DD + s * 32;
        const float* wp2 = w + j * DD + s * 32;
        const float* wsp = ws + s * 32;
        float p1 = 0.f, p2 = 0.f;
        #pragma unroll
        for (int i = 0; i < 32; ++i) {
            float wv = wsp[i];
            p1 = fmaf(wv, up[i], p1);
            p2 = fmaf(wv, wp2[i], p2);
        }
        #pragma unroll
        for (int o = 1; o <= 4; o <<= 1) {
            p1 += __shfl_xor_sync(0xffffffffu, p1, o);
            p2 += __shfl_xor_sync(0xffffffffu, p2, o);
        }
        if (s == 0) {
            g_G1[k * KK + j] = p1;
            g_G2[k * KK + j] = p2;
        }
    }
    __syncthreads();

    // uhat_k needs alpha_k = f(G1[k][k], G2[k][k]) just computed by warp k... 
    // G1[k][k] was written by thread j=k group; re-read from global after sync.
    __shared__ float s_alpha;
    if (t == 0) {
        float wu = g_G1[k * (KK + 1)];
        float ww = g_G2[k * (KK + 1)];
        s_alpha = (softplus(wu) - 1.0f - wu) / ww;
    }
    __syncthreads();
    g_uhat[k * DD + t] = fmaf(s_alpha, ws[t], u[k * DD + t]);
}

// ---------- A kernel: A[k][j] = G1[k][j] + alpha_j * G2[k][j] (1 block) ----------
__global__ __launch_bounds__(1024, 1)
void k_A2() {
    const int t = threadIdx.x;           // 1024 = 32x32
    const int k = t >> 5, j = t & 31;
    float wu = g_G1[j * (KK + 1)];
    float ww = g_G2[j * (KK + 1)];
    float al = (softplus(wu) - 1.0f - wu) / ww;
    g_A[k * KK + j] = fmaf(al, g_G2[k * KK + j], g_G1[k * KK + j]);
}

// ---------- Main monolith: 256 threads, TM=64, 2 blocks/SM ----------
// smem (floats):
//  XS : 0      X tile [r][d] stride 260 (float4-clean)     = 16640
//    after phase 1 XS is dead; aliases:
//      UH = 0      uhat [k][d] linear                      (8192)
//      TS = 8192   t [r][k] stride 36                      (2304)
//      AS = 10496  A[k][j]                                 (1024)
//  WT : 16640  W^T [d][k] stride 36 (dead after phase 1)   = 9216
//  CS : 25856  C [r][k] stride 34                          = 2176
//  BS : 28032  b[32]
// total 28064 floats = 112256 B -> 2 blocks/SM
#define OFF_XS 0
#define OFF_UH 0
#define OFF_TS 8192
#define OFF_AS 10496
#define OFF_WT 16640
#define OFF_CS 25856
#define OFF_BS 28032
#define SMEM_FLOATS 28064

__global__ __launch_bounds__(256, 2)
void nf_main(const float* __restrict__ X, const float* __restrict__ bvec,
             float* __restrict__ out) {
    extern __shared__ float sm[];
    float* XS = sm + OFF_XS;
    float* UH = sm + OFF_UH;
    float* TS = sm + OFF_TS;
    float* AS = sm + OFF_AS;
    float* WT = sm + OFF_WT;
    float* CS = sm + OFF_CS;
    float* BS = sm + OFF_BS;

    const int t = threadIdx.x;
    const int r0 = blockIdx.x * TM;

    // ---- Prologue: stage X (float4), W^T (stride 36), b ----
    {
        const float4* Xb4 = (const float4*)(X + (size_t)r0 * DD);
        #pragma unroll
        for (int i = t; i < TM * DD / 4; i += 256) {
            int r = i >> 6, d4 = i & 63;
            *(float4*)&XS[r * 260 + d4 * 4] = Xb4[i];
        }
        const float4* W4 = (const float4*)g_WT;
        #pragma unroll
        for (int i = t; i < KK * DD / 4; i += 256) {
            int d = i >> 3, k4 = i & 7;
            *(float4*)&WT[d * 36 + k4 * 4] = W4[i];
        }
        if (t < KK) BS[t] = bvec[t];
    }
    __syncthreads();

    // ---- Phase 1: C = X . W^T ----
    // warp = (row-half rh, k-group kg of 8); lane = row within half; full d.
    {
        const int wp = t >> 5, lane = t & 31;
        const int rh = wp >> 2, kg = wp & 3;
        const int row = rh * 32 + lane;
        ull c0 = 0ull, c1 = 0ull, c2 = 0ull, c3 = 0ull;
        const float* xrow = XS + row * 260;
        const float* wcol = WT + kg * 8;
        #pragma unroll 16
        for (int d = 0; d < DD; d += 4) {
            float4 xv = *(const float4*)(xrow + d);
            #pragma unroll
            for (int j = 0; j < 4; ++j) {
                ulonglong2 wa = *(const ulonglong2*)(wcol + (d + j) * 36);
                ulonglong2 wb = *(const ulonglong2*)(wcol + (d + j) * 36 + 4);
                float xj = (&xv.x)[j];
                ull xx = packf2(xj, xj);
                c0 = ffma2(xx, wa.x, c0);
                c1 = ffma2(xx, wa.y, c1);
                c2 = ffma2(xx, wb.x, c2);
                c3 = ffma2(xx, wb.y, c3);
            }
        }
        float* cr = CS + row * 34 + kg * 8;
        *(ull*)&cr[0] = c0;
        *(ull*)&cr[2] = c1;
        *(ull*)&cr[4] = c2;
        *(ull*)&cr[6] = c3;
    }
    __syncthreads();

    // ---- Stage A into smem (XS dead now; fast, then barrier) ----
    if (t >= TM) {
        const float4* A4 = (const float4*)g_A;
        for (int i = t - TM; i < KK * KK / 4; i += 256 - TM)
            *(float4*)&AS[i * 4] = A4[i];
    }
    __syncthreads();

    // ---- Phase 2: warps 0-1 recurrence; warps 2-7 stage uhat over XS ----
    if (t < TM) {
        const int row = t;
        float tl[KK];
        #pragma unroll
        for (int k = 0; k < KK; ++k) {
            float lin = CS[row * 34 + k] + BS[k];
            #pragma unroll
            for (int j = 0; j < k; ++j)
                lin = fmaf(AS[k * KK + j], tl[j], lin);
            float tk = ftanh(lin);
            tl[k] = tk;
            TS[row * 36 + k] = tk;
            float akk = AS[k * (KK + 1)];
            out[BD + k * BB + r0 + row] =
                __logf(fabsf(fmaf(1.0f - tk * tk, akk, 1.0f)) + 1e-8f);
        }
    } else {
        const float4* U4 = (const float4*)g_uhat;
        float4* UH4 = (float4*)UH;
        for (int i = t - TM; i < KK * DD / 4; i += 256 - TM)
            UH4[i] = U4[i];
    }
    __syncthreads();

    // ---- Phase 3: Z = X + T . Uhat ----
    // warp owns 8 rows; accumulators init from global X (coalesced, L2-warm).
    {
        const int lane = t & 31, wp = t >> 5;
        const int c0 = lane * 4, c1 = 128 + lane * 4;
        const int rb = wp * 8;
        ulonglong2 a[8][2];
        #pragma unroll
        for (int r = 0; r < 8; ++r) {
            const float* xr = X + (size_t)(r0 + rb + r) * DD;
            a[r][0] = *(const ulonglong2*)(xr + c0);
            a[r][1] = *(const ulonglong2*)(xr + c1);
        }
        #pragma unroll 4
        for (int kh = 0; kh < 16; ++kh) {       // 2 k per step
            const int k0 = kh * 2;
            float2 tv[8];
            #pragma unroll
            for (int r = 0; r < 8; ++r)
                tv[r] = *(const float2*)&TS[(rb + r) * 36 + k0];
            #pragma unroll
            for (int kk = 0; kk < 2; ++kk) {
                const int k = k0 + kk;
                ulonglong2 u0 = *(const ulonglong2*)&UH[k * DD + c0];
                ulonglong2 u1 = *(const ulonglong2*)&UH[k * DD + c1];
                #pragma unroll
                for (int r = 0; r < 8; ++r) {
                    float ts = kk ? tv[r].y : tv[r].x;
                    ull tt = packf2(ts, ts);
                    a[r][0].x = ffma2(tt, u0.x, a[r][0].x);
                    a[r][0].y = ffma2(tt, u0.y, a[r][0].y);
                    a[r][1].x = ffma2(tt, u1.x, a[r][1].x);
                    a[r][1].y = ffma2(tt, u1.y, a[r][1].y);
                }
            }
        }
        #pragma unroll
        for (int r = 0; r < 8; ++r) {
            float* zr = out + (size_t)(r0 + rb + r) * DD;
            *(ulonglong2*)(zr + c0) = a[r][0];
            *(ulonglong2*)(zr + c1) = a[r][1];
        }
    }
}

extern "C" void kernel_launch(void* const* d_in, const int* in_sizes, int n_in,
                              void* d_out, int out_size) {
    const float* X = (const float*)d_in[0];
    // d_in[1] = h (unused)
    const float* u = (const float*)d_in[2];
    const float* w = (const float*)d_in[3];
    const float* b = (const float*)d_in[4];
    float* out = (float*)d_out;

    cudaFuncSetAttribute(nf_main, cudaFuncAttributeMaxDynamicSharedMemorySize,
                         SMEM_FLOATS * (int)sizeof(float));

    k_gram<<<KK, 256>>>(u, w);
    k_A2<<<1, 1024>>>();
    nf_main<<<NBLK, 256, SMEM_FLOATS * sizeof(float)>>>(X, b, out);
}

// round 14
// speedup vs baseline: 1.7476x; 1.2296x over previous
#include <cuda_runtime.h>

// Problem constants
#define BB 65536
#define DD 256
#define KK 32
#define TM 64
#define NBLK (BB / TM)   // 1024
#define BD (BB * DD)

// Device scratch (no cudaMalloc allowed)
__device__ float g_G1[KK * KK];                    // W . U^T
__device__ float g_G2[KK * KK];                    // W . W^T
__device__ float g_AL[KK];                         // alpha_k
__device__ __align__(16) float g_uhat[KK * DD];    // [k][d]
__device__ __align__(16) float g_WT[DD * KK];      // W transposed [d][k]

typedef unsigned long long ull;

// ---------- f32x2 helpers ----------
__device__ __forceinline__ ull ffma2(ull a, ull b, ull c) {
    ull d;
    asm("fma.rn.f32x2 %0, %1, %2, %3;" : "=l"(d) : "l"(a), "l"(b), "l"(c));
    return d;
}
__device__ __forceinline__ ull fadd2(ull a, ull b) {
    ull d;
    asm("add.rn.f32x2 %0, %1, %2;" : "=l"(d) : "l"(a), "l"(b));
    return d;
}
__device__ __forceinline__ ull packf2(float x, float y) {
    ull r;
    asm("mov.b64 %0, {%1, %2};" : "=l"(r) : "f"(x), "f"(y));
    return r;
}

// fast accurate tanh: 1 - 2/(exp(2x)+1)
__device__ __forceinline__ float ftanh(float x) {
    float e = __expf(2.0f * x);
    return 1.0f - __fdividef(2.0f, e + 1.0f);
}

__device__ __forceinline__ float softplus(float x) {
    return fmaxf(x, 0.f) + log1pf(expf(-fabsf(x)));
}

// ---------- Gram kernel (block = k): G1/G2 rows, alpha_k, uhat_k, W^T ----------
__global__ __launch_bounds__(256, 4)
void k_gram(const float* __restrict__ u, const float* __restrict__ w) {
    __shared__ float ws[DD];
    __shared__ float red[16];
    __shared__ float s_alpha;
    const int k = blockIdx.x, t = threadIdx.x;
    const int lane = t & 31, wp = t >> 5;

    float wv_t = w[k * DD + t];
    float uv_t = u[k * DD + t];
    ws[t] = wv_t;
    g_WT[t * KK + k] = wv_t;

    // alpha_k from in-block reduction (no global round trip)
    {
        float p = wv_t * uv_t;
        float q = wv_t * wv_t;
        #pragma unroll
        for (int o = 16; o; o >>= 1) {
            p += __shfl_xor_sync(0xffffffffu, p, o);
            q += __shfl_xor_sync(0xffffffffu, q, o);
        }
        if (lane == 0) { red[wp * 2] = p; red[wp * 2 + 1] = q; }
    }
    __syncthreads();
    if (t == 0) {
        float wu = 0.f, ww = 0.f;
        #pragma unroll
        for (int i = 0; i < 8; ++i) { wu += red[2 * i]; ww += red[2 * i + 1]; }
        float a = (softplus(wu) - 1.0f - wu) / ww;
        s_alpha = a;
        g_AL[k] = a;
    }
    __syncthreads();
    g_uhat[k * DD + t] = fmaf(s_alpha, wv_t, uv_t);

    // Gram rows: warp wp handles j = wp*4 .. wp*4+3; lane owns 8-d chunk
    #pragma unroll
    for (int jj = 0; jj < 4; ++jj) {
        const int j = wp * 4 + jj;
        const float* up  = u + j * DD + lane * 8;
        const float* wp2 = w + j * DD + lane * 8;
        const float* wsp = ws + lane * 8;
        float p1 = 0.f, p2 = 0.f;
        #pragma unroll
        for (int i = 0; i < 8; ++i) {
            float wv = wsp[i];
            p1 = fmaf(wv, up[i], p1);
            p2 = fmaf(wv, wp2[i], p2);
        }
        #pragma unroll
        for (int o = 16; o; o >>= 1) {
            p1 += __shfl_xor_sync(0xffffffffu, p1, o);
            p2 += __shfl_xor_sync(0xffffffffu, p2, o);
        }
        if (lane == 0) {
            g_G1[k * KK + j] = p1;
            g_G2[k * KK + j] = p2;
        }
    }
}

// ---------- Main monolith: 256 threads, TM=64, 2 blocks/SM ----------
// smem (floats):
//  XS : 0      X tile [r][d] stride 260 (float4-clean)    = 16640
//    dead after phase 1; aliases:
//      UH = 0      uhat [k][d] linear                     (8192)
//      AS = 8192   A[k][j]                                (1024)
//  WT : 16640  W^T [d][k] stride 36 (dead after phase 1)  = 9216
//  CS : 25856  C [r][k] stride 34; t overwrites in place  = 2176
//  BS : 28032  b[32],  AL : 28064 alpha[32]
// total 28096 floats = 112384 B -> 2 blocks/SM
#define OFF_XS 0
#define OFF_UH 0
#define OFF_AS 8192
#define OFF_WT 16640
#define OFF_CS 25856
#define OFF_BS 28032
#define OFF_AL 28064
#define SMEM_FLOATS 28096

__global__ __launch_bounds__(256, 2)
void nf_main(const float* __restrict__ X, const float* __restrict__ bvec,
             float* __restrict__ out) {
    extern __shared__ float sm[];
    float* XS = sm + OFF_XS;
    float* UH = sm + OFF_UH;
    float* AS = sm + OFF_AS;
    float* WT = sm + OFF_WT;
    float* CS = sm + OFF_CS;
    float* BS = sm + OFF_BS;
    float* AL = sm + OFF_AL;

    const int t = threadIdx.x;
    const int r0 = blockIdx.x * TM;
    const int lane = t & 31, wp = t >> 5;

    // ---- Prologue: stage X (float4), W^T (stride 36), b, alpha ----
    {
        const float4* Xb4 = (const float4*)(X + (size_t)r0 * DD);
        #pragma unroll
        for (int i = t; i < TM * DD / 4; i += 256) {
            int r = i >> 6, d4 = i & 63;
            *(float4*)&XS[r * 260 + d4 * 4] = Xb4[i];
        }
        const float4* W4 = (const float4*)g_WT;
        #pragma unroll
        for (int i = t; i < KK * DD / 4; i += 256) {
            int d = i >> 3, k4 = i & 7;
            *(float4*)&WT[d * 36 + k4 * 4] = W4[i];
        }
        if (t < KK) { BS[t] = bvec[t]; AL[t] = g_AL[t]; }
    }
    __syncthreads();

    // ---- Phase 1: C = X . W^T ----
    // warp = (d-half dh, k-group kg of 8); lane = rows lane, lane+32
    ull c0[4], c1[4];
    {
        const int dh = wp >> 2, kg = wp & 3;
        const int d0 = dh * 128;
        #pragma unroll
        for (int q = 0; q < 4; ++q) { c0[q] = 0ull; c1[q] = 0ull; }
        const float* x0p = XS + lane * 260 + d0;
        const float* x1p = XS + (lane + 32) * 260 + d0;
        const float* wcol = WT + kg * 8 + d0 * 36;
        #pragma unroll 8
        for (int dd = 0; dd < 128; dd += 4) {
            float4 xa = *(const float4*)(x0p + dd);
            float4 xb = *(const float4*)(x1p + dd);
            #pragma unroll
            for (int j = 0; j < 4; ++j) {
                ulonglong2 wa = *(const ulonglong2*)(wcol + (dd + j) * 36);
                ulonglong2 wb = *(const ulonglong2*)(wcol + (dd + j) * 36 + 4);
                float xj0 = (&xa.x)[j];
                float xj1 = (&xb.x)[j];
                ull p0 = packf2(xj0, xj0);
                ull p1 = packf2(xj1, xj1);
                c0[0] = ffma2(p0, wa.x, c0[0]);
                c0[1] = ffma2(p0, wa.y, c0[1]);
                c0[2] = ffma2(p0, wb.x, c0[2]);
                c0[3] = ffma2(p0, wb.y, c0[3]);
                c1[0] = ffma2(p1, wa.x, c1[0]);
                c1[1] = ffma2(p1, wa.y, c1[1]);
                c1[2] = ffma2(p1, wb.x, c1[2]);
                c1[3] = ffma2(p1, wb.y, c1[3]);
            }
        }
        // d-half 0 stores its partials
        if (dh == 0) {
            const int k0 = kg * 8;
            #pragma unroll
            for (int q = 0; q < 4; ++q) {
                *(ull*)&CS[lane * 34 + k0 + 2 * q]        = c0[q];
                *(ull*)&CS[(lane + 32) * 34 + k0 + 2 * q] = c1[q];
            }
        }
    }
    __syncthreads();

    // d-half 1 accumulates in place; warps 0-3 stage AS + start UH (XS dead)
    if (wp >= 4) {
        const int kg = wp & 3;
        const int k0 = kg * 8;
        #pragma unroll
        for (int q = 0; q < 4; ++q) {
            ull* a0 = (ull*)&CS[lane * 34 + k0 + 2 * q];
            ull* a1 = (ull*)&CS[(lane + 32) * 34 + k0 + 2 * q];
            *a0 = fadd2(*a0, c0[q]);
            *a1 = fadd2(*a1, c1[q]);
        }
    } else {
        // AS = G1 + alpha_j * G2  (warps 0-3: 1024 elems)
        for (int e = t; e < KK * KK; e += 128)
            AS[e] = fmaf(AL[e & 31], g_G2[e], g_G1[e]);
    }
    __syncthreads();

    // ---- Phase 2: warps 0-1 recurrence (t in-place over CS); 2-7 stage uhat ----
    if (t < TM) {
        const int row = t;
        float tl[KK];
        #pragma unroll
        for (int k = 0; k < KK; ++k) {
            float lin = CS[row * 34 + k] + BS[k];
            #pragma unroll
            for (int j = 0; j < k; ++j)
                lin = fmaf(AS[k * KK + j], tl[j], lin);
            float tk = ftanh(lin);
            tl[k] = tk;
            CS[row * 34 + k] = tk;   // overwrite C with t (slot is dead)
            float akk = AS[k * (KK + 1)];
            out[BD + k * BB + r0 + row] =
                __logf(fabsf(fmaf(1.0f - tk * tk, akk, 1.0f)) + 1e-8f);
        }
    } else {
        const float4* U4 = (const float4*)g_uhat;
        float4* UH4 = (float4*)UH;
        for (int i = t - TM; i < KK * DD / 4; i += 256 - TM)
            UH4[i] = U4[i];
    }
    __syncthreads();

    // ---- Phase 3: Z = X + T . Uhat ----
    // warp owns 8 rows; accumulators init from global X (coalesced, L2-warm).
    {
        const int col0 = lane * 4, col1 = 128 + lane * 4;
        const int rb = wp * 8;
        ulonglong2 a[8][2];
        #pragma unroll
        for (int r = 0; r < 8; ++r) {
            const float* xr = X + (size_t)(r0 + rb + r) * DD;
            a[r][0] = *(const ulonglong2*)(xr + col0);
            a[r][1] = *(const ulonglong2*)(xr + col1);
        }
        #pragma unroll 4
        for (int kh = 0; kh < 16; ++kh) {       // 2 k per step
            const int k0 = kh * 2;
            float2 tv[8];
            #pragma unroll
            for (int r = 0; r < 8; ++r)
                tv[r] = *(const float2*)&CS[(rb + r) * 34 + k0];
            #pragma unroll
            for (int kk = 0; kk < 2; ++kk) {
                const int k = k0 + kk;
                ulonglong2 u0 = *(const ulonglong2*)&UH[k * DD + col0];
                ulonglong2 u1 = *(const ulonglong2*)&UH[k * DD + col1];
                #pragma unroll
                for (int r = 0; r < 8; ++r) {
                    float ts = kk ? tv[r].y : tv[r].x;
                    ull tt = packf2(ts, ts);
                    a[r][0].x = ffma2(tt, u0.x, a[r][0].x);
                    a[r][0].y = ffma2(tt, u0.y, a[r][0].y);
                    a[r][1].x = ffma2(tt, u1.x, a[r][1].x);
                    a[r][1].y = ffma2(tt, u1.y, a[r][1].y);
                }
            }
        }
        #pragma unroll
        for (int r = 0; r < 8; ++r) {
            float* zr = out + (size_t)(r0 + rb + r) * DD;
            *(ulonglong2*)(zr + col0) = a[r][0];
            *(ulonglong2*)(zr + col1) = a[r][1];
        }
    }
}

extern "C" void kernel_launch(void* const* d_in, const int* in_sizes, int n_in,
                              void* d_out, int out_size) {
    const float* X = (const float*)d_in[0];
    // d_in[1] = h (unused)
    const float* u = (const float*)d_in[2];
    const float* w = (const float*)d_in[3];
    const float* b = (const float*)d_in[4];
    float* out = (float*)d_out;

    cudaFuncSetAttribute(nf_main, cudaFuncAttributeMaxDynamicSharedMemorySize,
                         SMEM_FLOATS * (int)sizeof(float));

    k_gram<<<KK, 256>>>(u, w);
    nf_main<<<NBLK, 256, SMEM_FLOATS * sizeof(float)>>>(X, b, out);
}

// round 16
// speedup vs baseline: 1.9362x; 1.1079x over previous
#include <cuda_runtime.h>

// Problem constants
#define BB 65536
#define DD 256
#define KK 32
#define TM 64
#define NBLK (BB / TM)   // 1024
#define BD (BB * DD)

// Device scratch (no cudaMalloc allowed)
__device__ float g_G1[KK * KK];                    // W . U^T
__device__ float g_G2[KK * KK];                    // W . W^T
__device__ float g_AL[KK];                         // alpha_k
__device__ __align__(16) float g_uhat[KK * DD];    // [k][d]
__device__ __align__(16) float g_WT[DD * KK];      // W transposed [d][k]
__device__ unsigned int g_done;                    // gram-completion flag (memset 0 per launch)

typedef unsigned long long ull;

// ---------- f32x2 helpers ----------
__device__ __forceinline__ ull ffma2(ull a, ull b, ull c) {
    ull d;
    asm("fma.rn.f32x2 %0, %1, %2, %3;" : "=l"(d) : "l"(a), "l"(b), "l"(c));
    return d;
}
__device__ __forceinline__ ull fadd2(ull a, ull b) {
    ull d;
    asm("add.rn.f32x2 %0, %1, %2;" : "=l"(d) : "l"(a), "l"(b));
    return d;
}
__device__ __forceinline__ ull packf2(float x, float y) {
    ull r;
    asm("mov.b64 %0, {%1, %2};" : "=l"(r) : "f"(x), "f"(y));
    return r;
}
__device__ __forceinline__ void cpasync16(void* smem_dst, const void* gsrc) {
    unsigned sa = (unsigned)__cvta_generic_to_shared(smem_dst);
    asm volatile("cp.async.cg.shared.global [%0], [%1], 16;" :: "r"(sa), "l"(gsrc));
}
__device__ __forceinline__ void cpasync_commit() {
    asm volatile("cp.async.commit_group;");
}
__device__ __forceinline__ void cpasync_waitall() {
    asm volatile("cp.async.wait_group 0;" ::: "memory");
}

// fast accurate tanh: 1 - 2/(exp(2x)+1)
__device__ __forceinline__ float ftanh(float x) {
    float e = __expf(2.0f * x);
    return 1.0f - __fdividef(2.0f, e + 1.0f);
}
__device__ __forceinline__ float softplus(float x) {
    return fmaxf(x, 0.f) + log1pf(expf(-fabsf(x)));
}

// ---------- Fused kernel ----------
// smem (floats):
//  XS : 0      X tile [r][d] stride 260 (float4-clean)    = 16640
//    dead after phase 1; aliases:
//      UH = 0      uhat [k][d] linear                     (8192)
//      AS = 8192   A[k][j]                                (1024)
//  WT : 16640  W^T [d][k] stride 36 (dead after phase 1)  = 9216
//              (pre-flag: gram scratch ws[256] lives here)
//  CS : 25856  C [r][k] stride 34; t overwrites in place  = 2176
//              (pre-flag: gram reduce scratch lives here)
//  BS : 28032  b[32],  AL : 28064 alpha[32]
// total 28096 floats = 112384 B -> 2 blocks/SM
#define OFF_XS 0
#define OFF_UH 0
#define OFF_AS 8192
#define OFF_WT 16640
#define OFF_CS 25856
#define OFF_BS 28032
#define OFF_AL 28064
#define SMEM_FLOATS 28096

__global__ __launch_bounds__(256, 2)
void nf_fused(const float* __restrict__ X, const float* __restrict__ uu,
              const float* __restrict__ w, const float* __restrict__ bvec,
              float* __restrict__ out) {
    extern __shared__ float sm[];
    float* XS = sm + OFF_XS;
    float* UH = sm + OFF_UH;
    float* AS = sm + OFF_AS;
    float* WT = sm + OFF_WT;
    float* CS = sm + OFF_CS;
    float* BS = sm + OFF_BS;
    float* AL = sm + OFF_AL;

    const int t = threadIdx.x;
    const int bid = blockIdx.x;
    const int r0 = bid * TM;
    const int lane = t & 31, wp = t >> 5;

    // ---- Stage X tile via cp.async (latency hides under gram/spin) ----
    {
        const float4* Xb4 = (const float4*)(X + (size_t)r0 * DD);
        #pragma unroll
        for (int i = t; i < TM * DD / 4; i += 256) {
            int r = i >> 6, d4 = i & 63;
            cpasync16(&XS[r * 260 + d4 * 4], &Xb4[i]);
        }
        cpasync_commit();
    }

    // ---- Blocks 0..31: gram work for k = bid ----
    if (bid < KK) {
        const int k = bid;
        float* ws  = WT;        // 256-float scratch (overwritten later by real WT)
        float* red = CS;        // reduce scratch

        float wv_t = w[k * DD + t];
        float uv_t = uu[k * DD + t];
        ws[t] = wv_t;
        g_WT[t * KK + k] = wv_t;

        // alpha_k
        {
            float p = wv_t * uv_t;
            float q = wv_t * wv_t;
            #pragma unroll
            for (int o = 16; o; o >>= 1) {
                p += __shfl_xor_sync(0xffffffffu, p, o);
                q += __shfl_xor_sync(0xffffffffu, q, o);
            }
            if (lane == 0) { red[wp * 2] = p; red[wp * 2 + 1] = q; }
        }
        __syncthreads();
        if (t == 0) {
            float wu = 0.f, ww = 0.f;
            #pragma unroll
            for (int i = 0; i < 8; ++i) { wu += red[2 * i]; ww += red[2 * i + 1]; }
            float a = (softplus(wu) - 1.0f - wu) / ww;
            red[16] = a;
            g_AL[k] = a;
        }
        __syncthreads();
        g_uhat[k * DD + t] = fmaf(red[16], wv_t, uv_t);

        // Gram rows: warp wp -> j = wp*4..wp*4+3; lane owns 8-d chunk (float4 x2)
        #pragma unroll
        for (int jj = 0; jj < 4; ++jj) {
            const int j = wp * 4 + jj;
            const float4* up4 = (const float4*)(uu + j * DD) + lane * 2;
            const float4* wp4 = (const float4*)(w  + j * DD) + lane * 2;
            const float*  wsp = ws + lane * 8;
            float4 ua = up4[0], ub = up4[1];
            float4 wa = wp4[0], wb = wp4[1];
            float p1 = 0.f, p2 = 0.f;
            #pragma unroll
            for (int i = 0; i < 4; ++i) {
                float wv0 = wsp[i], wv1 = wsp[4 + i];
                p1 = fmaf(wv0, (&ua.x)[i], p1);
                p2 = fmaf(wv0, (&wa.x)[i], p2);
                p1 = fmaf(wv1, (&ub.x)[i], p1);
                p2 = fmaf(wv1, (&wb.x)[i], p2);
            }
            #pragma unroll
            for (int o = 16; o; o >>= 1) {
                p1 += __shfl_xor_sync(0xffffffffu, p1, o);
                p2 += __shfl_xor_sync(0xffffffffu, p2, o);
            }
            if (lane == 0) {
                g_G1[k * KK + j] = p1;
                g_G2[k * KK + j] = p2;
            }
        }
        __threadfence();
        __syncthreads();
        if (t == 0) atomicAdd(&g_done, 1u);
    }

    // ---- All blocks: wait until all 32 gram blocks published ----
    if (t == 0) {
        while (atomicAdd(&g_done, 0u) < (unsigned)KK) __nanosleep(64);
    }
    __syncthreads();

    // ---- Stage W^T (stride 36) via cp.async; b, alpha ----
    {
        const float4* W4 = (const float4*)g_WT;
        #pragma unroll
        for (int i = t; i < KK * DD / 4; i += 256) {
            int d = i >> 3, k4 = i & 7;
            cpasync16(&WT[d * 36 + k4 * 4], &W4[i]);
        }
        cpasync_commit();
        if (t < KK) { BS[t] = bvec[t]; AL[t] = g_AL[t]; }
    }
    cpasync_waitall();      // X + WT complete
    __syncthreads();

    // ---- Phase 1: C = X . W^T ----
    // warp = (d-half dh, k-group kg of 8); lane = rows lane, lane+32
    ull c0[4], c1[4];
    {
        const int dh = wp >> 2, kg = wp & 3;
        const int d0 = dh * 128;
        #pragma unroll
        for (int q = 0; q < 4; ++q) { c0[q] = 0ull; c1[q] = 0ull; }
        const float* x0p = XS + lane * 260 + d0;
        const float* x1p = XS + (lane + 32) * 260 + d0;
        const float* wcol = WT + kg * 8 + d0 * 36;
        #pragma unroll 8
        for (int dd = 0; dd < 128; dd += 4) {
            float4 xa = *(const float4*)(x0p + dd);
            float4 xb = *(const float4*)(x1p + dd);
            #pragma unroll
            for (int j = 0; j < 4; ++j) {
                ulonglong2 wa = *(const ulonglong2*)(wcol + (dd + j) * 36);
                ulonglong2 wb = *(const ulonglong2*)(wcol + (dd + j) * 36 + 4);
                float xj0 = (&xa.x)[j];
                float xj1 = (&xb.x)[j];
                ull p0 = packf2(xj0, xj0);
                ull p1 = packf2(xj1, xj1);
                c0[0] = ffma2(p0, wa.x, c0[0]);
                c0[1] = ffma2(p0, wa.y, c0[1]);
                c0[2] = ffma2(p0, wb.x, c0[2]);
                c0[3] = ffma2(p0, wb.y, c0[3]);
                c1[0] = ffma2(p1, wa.x, c1[0]);
                c1[1] = ffma2(p1, wa.y, c1[1]);
                c1[2] = ffma2(p1, wb.x, c1[2]);
                c1[3] = ffma2(p1, wb.y, c1[3]);
            }
        }
        if (dh == 0) {
            const int k0 = kg * 8;
            #pragma unroll
            for (int q = 0; q < 4; ++q) {
                *(ull*)&CS[lane * 34 + k0 + 2 * q]        = c0[q];
                *(ull*)&CS[(lane + 32) * 34 + k0 + 2 * q] = c1[q];
            }
        }
    }
    __syncthreads();

    // d-half 1 accumulates in place; warps 0-3 compute AS (XS dead now)
    if (wp >= 4) {
        const int kg = wp & 3;
        const int k0 = kg * 8;
        #pragma unroll
        for (int q = 0; q < 4; ++q) {
            ull* a0 = (ull*)&CS[lane * 34 + k0 + 2 * q];
            ull* a1 = (ull*)&CS[(lane + 32) * 34 + k0 + 2 * q];
            *a0 = fadd2(*a0, c0[q]);
            *a1 = fadd2(*a1, c1[q]);
        }
    } else {
        for (int e = t; e < KK * KK; e += 128)
            AS[e] = fmaf(AL[e & 31], g_G2[e], g_G1[e]);
    }
    __syncthreads();

    // ---- Phase 2: warps 0-1 recurrence (4-way ILP); warps 2-7 stage uhat
    //      + hoist their phase-3 X-init loads above the barrier ----
    ulonglong2 a[8][2];
    const int col0 = lane * 4, col1 = 128 + lane * 4;
    const int rb = wp * 8;

    if (t < TM) {
        const int row = t;
        float tl[KK];
        #pragma unroll
        for (int k = 0; k < KK; ++k) {
            float la[4];
            la[0] = CS[row * 34 + k] + BS[k];
            la[1] = 0.f; la[2] = 0.f; la[3] = 0.f;
            #pragma unroll
            for (int j = 0; j < k; ++j)
                la[j & 3] = fmaf(AS[k * KK + j], tl[j], la[j & 3]);
            float lin = (la[0] + la[1]) + (la[2] + la[3]);
            float tk = ftanh(lin);
            tl[k] = tk;
            CS[row * 34 + k] = tk;   // overwrite C with t (slot is dead)
            float akk = AS[k * (KK + 1)];
            out[BD + k * BB + r0 + row] =
                __logf(fabsf(fmaf(1.0f - tk * tk, akk, 1.0f)) + 1e-8f);
        }
    } else {
        const float4* U4 = (const float4*)g_uhat;
        float4* UH4 = (float4*)UH;
        for (int i = t - TM; i < KK * DD / 4; i += 256 - TM)
            UH4[i] = U4[i];
    }
    // hoisted X-init for non-recurrence warps
    if (t >= TM) {
        #pragma unroll
        for (int r = 0; r < 8; ++r) {
            const float* xr = X + (size_t)(r0 + rb + r) * DD;
            a[r][0] = *(const ulonglong2*)(xr + col0);
            a[r][1] = *(const ulonglong2*)(xr + col1);
        }
    }
    __syncthreads();
    if (t < TM) {
        #pragma unroll
        for (int r = 0; r < 8; ++r) {
            const float* xr = X + (size_t)(r0 + rb + r) * DD;
            a[r][0] = *(const ulonglong2*)(xr + col0);
            a[r][1] = *(const ulonglong2*)(xr + col1);
        }
    }

    // ---- Phase 3: Z = X + T . Uhat ----
    {
        #pragma unroll 4
        for (int kh = 0; kh < 16; ++kh) {       // 2 k per step
            const int k0 = kh * 2;
            float2 tv[8];
            #pragma unroll
            for (int r = 0; r < 8; ++r)
                tv[r] = *(const float2*)&CS[(rb + r) * 34 + k0];
            #pragma unroll
            for (int kk = 0; kk < 2; ++kk) {
                const int k = k0 + kk;
                ulonglong2 u0 = *(const ulonglong2*)&UH[k * DD + col0];
                ulonglong2 u1 = *(const ulonglong2*)&UH[k * DD + col1];
                #pragma unroll
                for (int r = 0; r < 8; ++r) {
                    float ts = kk ? tv[r].y : tv[r].x;
                    ull tt = packf2(ts, ts);
                    a[r][0].x = ffma2(tt, u0.x, a[r][0].x);
                    a[r][0].y = ffma2(tt, u0.y, a[r][0].y);
                    a[r][1].x = ffma2(tt, u1.x, a[r][1].x);
                    a[r][1].y = ffma2(tt, u1.y, a[r][1].y);
                }
            }
        }
        #pragma unroll
        for (int r = 0; r < 8; ++r) {
            float* zr = out + (size_t)(r0 + rb + r) * DD;
            *(ulonglong2*)(zr + col0) = a[r][0];
            *(ulonglong2*)(zr + col1) = a[r][1];
        }
    }
}

extern "C" void kernel_launch(void* const* d_in, const int* in_sizes, int n_in,
                              void* d_out, int out_size) {
    const float* X = (const float*)d_in[0];
    // d_in[1] = h (unused)
    const float* u = (const float*)d_in[2];
    const float* w = (const float*)d_in[3];
    const float* b = (const float*)d_in[4];
    float* out = (float*)d_out;

    cudaFuncSetAttribute(nf_fused, cudaFuncAttributeMaxDynamicSharedMemorySize,
                         SMEM_FLOATS * (int)sizeof(float));

    // reset gram-completion flag (graph-capturable, no allocation)
    void* flag_ptr = nullptr;
    cudaGetSymbolAddress(&flag_ptr, g_done);
    cudaMemsetAsync(flag_ptr, 0, sizeof(unsigned int));

    nf_fused<<<NBLK, 256, SMEM_FLOATS * sizeof(float)>>>(X, u, w, b, out);
}